// round 9
// baseline (speedup 1.0000x reference)
#include <cuda_runtime.h>
#include <cstdint>

// BinaryTree hierarchical-softmax forward:
//   z = W[leaf(input)], path = 21 root-to-leaf nodes of context vertex
//   out[b] = prod_i sigmoid(dot(W[path_i], z)) = 1 / prod_i (1 + exp(-s_i))
//
// d_in[0]: collocation int32 [65536, 2]
// d_in[1]: W float32 [2097151, 128]
// d_out  : float32 [65536]
//
// Hot/cold split. Only ~5 rows per element actually miss to DRAM (z + path
// levels 17..20); levels 0..16 (67MB of 131K distinct rows) are L2-resident
// and the top levels L1-resident. So: pipeline ONLY the cold rows one element
// ahead (20 regs, issued at iteration start -> in flight the whole ~600cyc
// iteration = full-duty DRAM stream), and load the 17 hot rows just-in-time
// in two register chunks whose partials go straight to a padded smem
// transpose. Low register peak -> 5-6 blocks/SM instead of 4 -> more warps
// each holding a full cold burst. NO register cap (R5: caps spill the burst).

#define DEPTH   20
#define NPATH   21
#define OFFSET  1048575u             // (1<<DEPTH)-1
#define BATCH   65536
#define PITCH   36                   // floats; rows 16B-aligned, low conflict

__global__ __launch_bounds__(128)
void BinaryTree_65927747993695_kernel(const int* __restrict__ coll,
                                      const float* __restrict__ W,
                                      float* __restrict__ out)
{
    __shared__ float red[4][NPATH * PITCH];

    const int tid    = blockIdx.x * blockDim.x + threadIdx.x;
    const int gw     = tid >> 5;
    const int lane   = tid & 31;
    const int wib    = (threadIdx.x >> 5) & 3;
    const int stride = (gridDim.x * blockDim.x) >> 5;

    int e = gw;
    if (e >= BATCH) return;

    float* __restrict__ row = red[wib];

    // float4-unit bases; path "-1" folded into Wm1; lane slice folded in.
    const float4* __restrict__ Wl  = (const float4*)W + lane;
    const float4* __restrict__ Wm1 = Wl - 32;

    // --- prologue: coll for e, e+stride; cold rows (z + levels 17..20) of e ---
    int2 cv0 = __ldg((const int2*)coll + e);
    int  e1  = e + stride;
    int2 cv1 = make_int2(0, 0);
    if (e1 < BATCH) cv1 = __ldg((const int2*)coll + e1);

    float4 z, cw[4];
    unsigned b;
    {
        z = __ldg(Wl + (size_t)((unsigned)cv0.x + OFFSET) * 32);
        b = (unsigned)cv0.y + OFFSET + 1u;
#pragma unroll
        for (int j = 0; j < 4; ++j)                   // levels 17..20
            cw[j] = __ldg(Wm1 + (size_t)(b >> (3 - j)) * 32);
    }

    for (;;) {
        // prefetch coll two elements ahead
        const int e2 = e1 + stride;
        int2 cv2 = make_int2(0, 0);
        if (e2 < BATCH) cv2 = __ldg((const int2*)coll + e2);

        // --- cold dots of e (frees cw[]) ---
#pragma unroll
        for (int j = 0; j < 4; ++j)
            row[(17 + j) * PITCH + lane] =
                cw[j].x * z.x + cw[j].y * z.y + cw[j].z * z.z + cw[j].w * z.w;

        // --- issue next element's COLD burst immediately (full-duty DRAM) ---
        const bool have_next = (e1 < BATCH);
        float4 zn;
        unsigned bn = (unsigned)cv1.y + OFFSET + 1u;
        if (have_next) {
            zn = __ldg(Wl + (size_t)((unsigned)cv1.x + OFFSET) * 32);
#pragma unroll
            for (int j = 0; j < 4; ++j)
                cw[j] = __ldg(Wm1 + (size_t)(bn >> (3 - j)) * 32);
        }

        // --- hot chunk A: levels 0..7 (L1/L2 hits), burst then dots ---
        {
            float4 h[8];
#pragma unroll
            for (int i = 0; i < 8; ++i)
                h[i] = __ldg(Wm1 + (size_t)(b >> (DEPTH - i)) * 32);
#pragma unroll
            for (int i = 0; i < 8; ++i)
                row[i * PITCH + lane] =
                    h[i].x * z.x + h[i].y * z.y + h[i].z * z.z + h[i].w * z.w;
        }

        // --- hot chunk B: levels 8..16 ---
        {
            float4 h[9];
#pragma unroll
            for (int i = 0; i < 9; ++i)
                h[i] = __ldg(Wm1 + (size_t)(b >> (12 - i)) * 32);
#pragma unroll
            for (int i = 0; i < 9; ++i)
                row[(8 + i) * PITCH + lane] =
                    h[i].x * z.x + h[i].y * z.y + h[i].z * z.z + h[i].w * z.w;
        }

        __syncwarp();

        // --- lane l (<21) sums its level's 32 partials: 8 x LDS.128 ---
        float c = 1.0f;
        if (lane < NPATH) {
            const float4* r4 = (const float4*)(row + lane * PITCH);
            float4 p0 = r4[0], p1 = r4[1], p2 = r4[2], p3 = r4[3];
            float4 p4 = r4[4], p5 = r4[5], p6 = r4[6], p7 = r4[7];
            float s = ((p0.x + p0.y) + (p0.z + p0.w))
                    + ((p1.x + p1.y) + (p1.z + p1.w))
                    + ((p2.x + p2.y) + (p2.z + p2.w))
                    + ((p3.x + p3.y) + (p3.z + p3.w))
                    + ((p4.x + p4.y) + (p4.z + p4.w))
                    + ((p5.x + p5.y) + (p5.z + p5.w))
                    + ((p6.x + p6.y) + (p6.z + p6.w))
                    + ((p7.x + p7.y) + (p7.z + p7.w));
            c = 1.0f + __expf(-s);
        }
        __syncwarp();   // protects rows from next iteration's STS

        // 5-shuffle product over the warp, then reciprocal
#pragma unroll
        for (int o = 16; o > 0; o >>= 1)
            c *= __shfl_xor_sync(0xFFFFFFFFu, c, o);

        if (lane == 0) out[e] = __fdividef(1.0f, c);

        if (!have_next) return;
        e   = e1;
        e1  = e2;
        cv1 = cv2;
        z   = zn;
        b   = bn;
    }
}

extern "C" void kernel_launch(void* const* d_in, const int* in_sizes, int n_in,
                              void* d_out, int out_size)
{
    const int*   coll = (const int*)d_in[0];
    const float* W    = (const float*)d_in[1];
    float*       out  = (float*)d_out;

    // Exactly one resident wave: size grid from measured occupancy.
    const int threads = 128;
    int bpsm = 4;
    cudaOccupancyMaxActiveBlocksPerMultiprocessor(
        &bpsm, BinaryTree_65927747993695_kernel, threads, 0);
    if (bpsm < 1) bpsm = 1;
    long long blocks = (long long)bpsm * 148;
    if (blocks > BATCH / 4) blocks = BATCH / 4;
    BinaryTree_65927747993695_kernel<<<(int)blocks, threads>>>(coll, W, out);
}

// round 10
// speedup vs baseline: 1.2444x; 1.2444x over previous
#include <cuda_runtime.h>
#include <cstdint>

// BinaryTree hierarchical-softmax forward:
//   z = W[leaf(input)], path = 21 root-to-leaf nodes of context vertex
//   out[b] = prod_i sigmoid(dot(W[path_i], z)) = 1 / prod_i (1 + exp(-s_i))
//
// d_in[0]: collocation int32 [65536, 2]
// d_in[1]: W float32 [2097151, 128]
// d_out  : float32 [65536]
//
// Warp-PAIR per element. The proven R4 structure (full 22-row burst for the
// next element issued while the current one is reduced) is kept, but the
// burst is split across two warps: warp A holds even path levels (11 rows),
// warp B odd levels (10 rows); both hold z. Each warp's register file drops
// from ~128 to ~72 regs, doubling resident warps/SM while preserving total
// pipeline depth per element. Levels are interleaved so each warp carries
// ~half of the DRAM-miss rows (z + deep levels). Partial dots go to a
// double-buffered per-pair smem transpose; one named 64-thread barrier per
// element; warp A reduces (8 x LDS.128 per lane-row + 1 SIMT EX2 + 5-shuffle
// product) while warp B's next burst is already in flight.
// NO register cap (R5: caps spill the burst). Grid = one resident wave.

#define DEPTH   20
#define NPATH   21
#define OFFSET  1048575u             // (1<<DEPTH)-1
#define BATCH   65536
#define PITCH   36                   // floats; rows 16B-aligned, low conflict

__global__ __launch_bounds__(128)
void BinaryTree_65927747993695_kernel(const int* __restrict__ coll,
                                      const float* __restrict__ W,
                                      float* __restrict__ out)
{
    // [pair-in-block][buffer][level*PITCH + lane]
    __shared__ float red[2][2][NPATH * PITCH];

    const int lane    = threadIdx.x & 31;
    const int wid     = threadIdx.x >> 5;     // 0..3
    const int ploc    = wid >> 1;             // pair in block: 0,1
    const int half    = wid & 1;              // 0 = warp A, 1 = warp B
    const int pair    = blockIdx.x * 2 + ploc;
    const int npairs  = gridDim.x * 2;
    const int barid   = 1 + ploc;             // named barrier per pair

    // this warp's levels: i = 2k + half, k = 0..nlev-1
    const int nlev       = 11 - half;         // A: 11 levels, B: 10
    const int base_shift = DEPTH - half;      // shift = base_shift - 2k

    const float4* __restrict__ Wl  = (const float4*)W + lane;
    const float4* __restrict__ Wm1 = Wl - 32; // path "-1" folded in

    int e = pair;
    if (e >= BATCH) return;                   // uniform across the pair

    // --- prologue ---
    int2 cv0 = __ldg((const int2*)coll + e);
    int  e1  = e + npairs;
    int2 cv1 = make_int2(0, 0);
    if (e1 < BATCH) cv1 = __ldg((const int2*)coll + e1);

    float4 z, w[11];
    unsigned b;
    {
        z = __ldg(Wl + (size_t)((unsigned)cv0.x + OFFSET) * 32);
        b = (unsigned)cv0.y + OFFSET + 1u;
#pragma unroll
        for (int k = 0; k < 11; ++k)
            if (k < nlev)
                w[k] = __ldg(Wm1 + (size_t)(b >> (base_shift - 2 * k)) * 32);
    }

    int buf = 0;
    for (;;) {
        // prefetch coll two elements ahead
        const int e2 = e1 + npairs;
        int2 cv2 = make_int2(0, 0);
        if (e2 < BATCH) cv2 = __ldg((const int2*)coll + e2);

        // --- partial dots for this warp's levels -> smem (frees w[]) ---
        float* __restrict__ rowb = red[ploc][buf];
#pragma unroll
        for (int k = 0; k < 11; ++k)
            if (k < nlev)
                rowb[(2 * k + half) * PITCH + lane] =
                    w[k].x * z.x + w[k].y * z.y + w[k].z * z.z + w[k].w * z.w;

        // --- issue next element's half-burst into freed registers ---
        const bool have_next = (e1 < BATCH);
        const unsigned bn = (unsigned)cv1.y + OFFSET + 1u;
        if (have_next) {
            z = __ldg(Wl + (size_t)((unsigned)cv1.x + OFFSET) * 32);
#pragma unroll
            for (int k = 0; k < 11; ++k)
                if (k < nlev)
                    w[k] = __ldg(Wm1 + (size_t)(bn >> (base_shift - 2 * k)) * 32);
        }

        // pair barrier: all 21 partial rows visible
        asm volatile("bar.sync %0, %1;" :: "r"(barid), "r"(64) : "memory");

        // --- warp A reduces while warp B's burst flies ---
        if (half == 0) {
            float c = 1.0f;
            if (lane < NPATH) {
                const float4* r4 = (const float4*)(rowb + lane * PITCH);
                float4 p0 = r4[0], p1 = r4[1], p2 = r4[2], p3 = r4[3];
                float4 p4 = r4[4], p5 = r4[5], p6 = r4[6], p7 = r4[7];
                float s = ((p0.x + p0.y) + (p0.z + p0.w))
                        + ((p1.x + p1.y) + (p1.z + p1.w))
                        + ((p2.x + p2.y) + (p2.z + p2.w))
                        + ((p3.x + p3.y) + (p3.z + p3.w))
                        + ((p4.x + p4.y) + (p4.z + p4.w))
                        + ((p5.x + p5.y) + (p5.z + p5.w))
                        + ((p6.x + p6.y) + (p6.z + p6.w))
                        + ((p7.x + p7.y) + (p7.z + p7.w));
                c = 1.0f + __expf(-s);
            }
#pragma unroll
            for (int o = 16; o > 0; o >>= 1)
                c *= __shfl_xor_sync(0xFFFFFFFFu, c, o);
            if (lane == 0) out[e] = __fdividef(1.0f, c);
        }

        if (!have_next) return;
        e   = e1;
        e1  = e2;
        cv1 = cv2;
        b   = bn;
        buf ^= 1;                 // double buffer: next STS never races A's reads
    }
}

extern "C" void kernel_launch(void* const* d_in, const int* in_sizes, int n_in,
                              void* d_out, int out_size)
{
    const int*   coll = (const int*)d_in[0];
    const float* W    = (const float*)d_in[1];
    float*       out  = (float*)d_out;

    // Exactly one resident wave: size grid from measured occupancy.
    const int threads = 128;
    int bpsm = 4;
    cudaOccupancyMaxActiveBlocksPerMultiprocessor(
        &bpsm, BinaryTree_65927747993695_kernel, threads, 0);
    if (bpsm < 1) bpsm = 1;
    long long blocks = (long long)bpsm * 148;
    if (blocks > BATCH / 2) blocks = BATCH / 2;
    BinaryTree_65927747993695_kernel<<<(int)blocks, threads>>>(coll, W, out);
}

// round 11
// speedup vs baseline: 1.5068x; 1.2108x over previous
#include <cuda_runtime.h>
#include <cstdint>

// BinaryTree hierarchical-softmax forward:
//   z = W[leaf(input)], path = 21 root-to-leaf nodes of context vertex
//   out[b] = prod_i sigmoid(dot(W[path_i], z)) = 1 / prod_i (1 + exp(-s_i))
//
// d_in[0]: collocation int32 [65536, 2]
// d_in[1]: W float32 [2097151, 128]
// d_out  : float32 [65536]
//
// R4 pipeline with a right-sized prefetch set. The register file is the
// landing buffer for in-flight rows; R4 burns 88 regs/thread keeping ALL 22
// rows in deep flight, pinning occupancy at 16 warps/SM. But only z +
// levels 7..20 (15 rows) have L2/DRAM latency; levels 0..6 are 127 rows =
// 63.5KB, L1-resident on every SM (~39cyc). So: prefetch the 15 deep rows
// one element ahead (60 regs, full-iteration flight), JIT-load levels 0..6
// as a 7-LDG L1 burst at iteration start. Peak regs ~100 -> 5 blocks/SM.
// Pruned 23-shuffle transpose-reduce, placed entirely AFTER the next deep
// burst is issued (interleaving it bloats regs to 146 — R6). No smem, no
// named barriers, NO register cap (R5: caps spill the burst).

#define DEPTH   20
#define NPATH   21
#define OFFSET  1048575u             // (1<<DEPTH)-1
#define BATCH   65536
#define NSHAL   7                    // JIT levels 0..6 (L1-resident)
#define NDEEP   14                   // prefetched path levels 7..20

__global__ __launch_bounds__(128)
void BinaryTree_65927747993695_kernel(const int* __restrict__ coll,
                                      const float* __restrict__ W,
                                      float* __restrict__ out)
{
    const int tid    = blockIdx.x * blockDim.x + threadIdx.x;
    const int gw     = tid >> 5;
    const int lane   = tid & 31;
    const int stride = (gridDim.x * blockDim.x) >> 5;

    int e = gw;
    if (e >= BATCH) return;

    // float4-unit bases; path "-1" folded into Wm1; lane slice folded in.
    const float4* __restrict__ Wl  = (const float4*)W + lane;
    const float4* __restrict__ Wm1 = Wl - 32;

    // --- prologue: coll for e, e+stride; deep rows (z + levels 7..20) of e ---
    int2 cv0 = __ldg((const int2*)coll + e);
    int  e1  = e + stride;
    int2 cv1 = make_int2(0, 0);
    if (e1 < BATCH) cv1 = __ldg((const int2*)coll + e1);

    float4 z, w[NDEEP];
    unsigned b;
    {
        z = __ldg(Wl + (size_t)((unsigned)cv0.x + OFFSET) * 32);
        b = (unsigned)cv0.y + OFFSET + 1u;
#pragma unroll
        for (int j = 0; j < NDEEP; ++j)          // level 7+j: shift = 13-j
            w[j] = __ldg(Wm1 + (size_t)(b >> (NDEEP - 1 - j)) * 32);
    }

    for (;;) {
        // prefetch coll two elements ahead
        const int e2 = e1 + stride;
        int2 cv2 = make_int2(0, 0);
        if (e2 < BATCH) cv2 = __ldg((const int2*)coll + e2);

        // --- JIT shallow burst: levels 0..6 (L1 hits, ~40cyc, overlapped) ---
        float4 h[NSHAL];
#pragma unroll
        for (int i = 0; i < NSHAL; ++i)
            h[i] = __ldg(Wm1 + (size_t)(b >> (DEPTH - i)) * 32);

        // --- partial dot products (frees h[], w[], z) ---
        float a[25];
#pragma unroll
        for (int i = 0; i < NSHAL; ++i)
            a[i] = h[i].x * z.x + h[i].y * z.y + h[i].z * z.z + h[i].w * z.w;
#pragma unroll
        for (int j = 0; j < NDEEP; ++j)
            a[NSHAL + j] = w[j].x * z.x + w[j].y * z.y + w[j].z * z.z + w[j].w * z.w;
        a[21] = 0.0f; a[22] = 0.0f; a[24] = 0.0f;

        // --- issue next element's deep burst into the freed registers ---
        const bool have_next = (e1 < BATCH);
        if (have_next) {
            z = __ldg(Wl + (size_t)((unsigned)cv1.x + OFFSET) * 32);
            const unsigned bn = (unsigned)cv1.y + OFFSET + 1u;
#pragma unroll
            for (int j = 0; j < NDEEP; ++j)
                w[j] = __ldg(Wm1 + (size_t)(bn >> (NDEEP - 1 - j)) * 32);
            b = bn;
        }

        // --- pruned compaction transpose-reduce (23 shuffles), all after burst ---
        {
            const bool hi = (lane & 1) != 0;
#pragma unroll
            for (int k = 0; k < NPATH; k += 2) {
                const float send = hi ? a[k] : a[k + 1];
                const float recv = __shfl_xor_sync(0xFFFFFFFFu, send, 1);
                a[k] = (hi ? a[k + 1] : a[k]) + recv;
            }
        }
        {
            const bool hi = (lane & 2) != 0;
#pragma unroll
            for (int k = 0; k < NPATH; k += 4) {
                const float send = hi ? a[k] : a[k + 2];
                const float recv = __shfl_xor_sync(0xFFFFFFFFu, send, 2);
                a[k] = (hi ? a[k + 2] : a[k]) + recv;
            }
        }
        {
            const bool hi = (lane & 4) != 0;
#pragma unroll
            for (int k = 0; k < NPATH; k += 8) {
                const float send = hi ? a[k] : a[k + 4];
                const float recv = __shfl_xor_sync(0xFFFFFFFFu, send, 4);
                a[k] = (hi ? a[k + 4] : a[k]) + recv;
            }
        }
        {
            const bool hi = (lane & 8) != 0;
#pragma unroll
            for (int k = 0; k < NPATH; k += 16) {
                const float send = hi ? a[k] : a[k + 8];
                const float recv = __shfl_xor_sync(0xFFFFFFFFu, send, 8);
                a[k] = (hi ? a[k + 8] : a[k]) + recv;
            }
        }
        {
            const bool hi = (lane & 16) != 0;
            const float send = hi ? a[0] : a[16];
            const float recv = __shfl_xor_sync(0xFFFFFFFFu, send, 16);
            a[0] = (hi ? a[16] : a[0]) + recv;
        }

        // lane l (< 21) holds s_l; one SIMT EX2 covers all levels
        float c = (lane < NPATH) ? (1.0f + __expf(-a[0])) : 1.0f;
#pragma unroll
        for (int o = 16; o > 0; o >>= 1)
            c *= __shfl_xor_sync(0xFFFFFFFFu, c, o);

        if (lane == 0) out[e] = __fdividef(1.0f, c);

        if (!have_next) return;
        e   = e1;
        e1  = e2;
        cv1 = cv2;
    }
}

extern "C" void kernel_launch(void* const* d_in, const int* in_sizes, int n_in,
                              void* d_out, int out_size)
{
    const int*   coll = (const int*)d_in[0];
    const float* W    = (const float*)d_in[1];
    float*       out  = (float*)d_out;

    // Exactly one resident wave: size grid from measured occupancy.
    const int threads = 128;
    int bpsm = 4;
    cudaOccupancyMaxActiveBlocksPerMultiprocessor(
        &bpsm, BinaryTree_65927747993695_kernel, threads, 0);
    if (bpsm < 1) bpsm = 1;
    long long blocks = (long long)bpsm * 148;
    if (blocks > BATCH / 4) blocks = BATCH / 4;
    BinaryTree_65927747993695_kernel<<<(int)blocks, threads>>>(coll, W, out);
}

// round 12
// speedup vs baseline: 1.5440x; 1.0247x over previous
#include <cuda_runtime.h>
#include <cstdint>

// BinaryTree hierarchical-softmax forward:
//   z = W[leaf(input)], path = 21 root-to-leaf nodes of context vertex
//   out[b] = prod_i sigmoid(dot(W[path_i], z)) = 1 / prod_i (1 + exp(-s_i))
//
// d_in[0]: collocation int32 [65536, 2]
// d_in[1]: W float32 [2097151, 128]
// d_out  : float32 [65536]
//
// R11 pipeline (deep rows z + levels 7..20 prefetched one element ahead,
// levels 0..6 JIT from L1, pruned compaction reduce after the burst) with
// the occupancy cliff removed: 64-thread (2-warp) blocks make warps/SM =
// floor(64K / (regs*64)) * 2, so register count trades against warps
// LINEARLY instead of in steps of 4 warps. Register trims: a[21] with
// explicit zero partners (was a[25]) and 4+3 chunked shallow loads.
// No smem, no named barriers, NO register cap (R5: caps spill the burst).

#define DEPTH   20
#define NPATH   21
#define OFFSET  1048575u             // (1<<DEPTH)-1
#define BATCH   65536
#define NDEEP   14                   // prefetched path levels 7..20

__global__ __launch_bounds__(64)
void BinaryTree_65927747993695_kernel(const int* __restrict__ coll,
                                      const float* __restrict__ W,
                                      float* __restrict__ out)
{
    const int tid    = blockIdx.x * blockDim.x + threadIdx.x;
    const int gw     = tid >> 5;
    const int lane   = tid & 31;
    const int stride = (gridDim.x * blockDim.x) >> 5;

    int e = gw;
    if (e >= BATCH) return;

    // float4-unit bases; path "-1" folded into Wm1; lane slice folded in.
    const float4* __restrict__ Wl  = (const float4*)W + lane;
    const float4* __restrict__ Wm1 = Wl - 32;

    // --- prologue: coll for e, e+stride; deep rows (z + levels 7..20) of e ---
    int2 cv0 = __ldg((const int2*)coll + e);
    int  e1  = e + stride;
    int2 cv1 = make_int2(0, 0);
    if (e1 < BATCH) cv1 = __ldg((const int2*)coll + e1);

    float4 z, w[NDEEP];
    unsigned b;
    {
        z = __ldg(Wl + (size_t)((unsigned)cv0.x + OFFSET) * 32);
        b = (unsigned)cv0.y + OFFSET + 1u;
#pragma unroll
        for (int j = 0; j < NDEEP; ++j)          // level 7+j: shift = 13-j
            w[j] = __ldg(Wm1 + (size_t)(b >> (NDEEP - 1 - j)) * 32);
    }

    for (;;) {
        // prefetch coll two elements ahead
        const int e2 = e1 + stride;
        int2 cv2 = make_int2(0, 0);
        if (e2 < BATCH) cv2 = __ldg((const int2*)coll + e2);

        float a[NPATH];

        // --- JIT shallow levels 0..6 (L1 hits), in 4+3 chunks to cap regs ---
        {
            float4 h0 = __ldg(Wm1 + (size_t)(b >> DEPTH) * 32);
            float4 h1 = __ldg(Wm1 + (size_t)(b >> (DEPTH - 1)) * 32);
            float4 h2 = __ldg(Wm1 + (size_t)(b >> (DEPTH - 2)) * 32);
            float4 h3 = __ldg(Wm1 + (size_t)(b >> (DEPTH - 3)) * 32);
            a[0] = h0.x * z.x + h0.y * z.y + h0.z * z.z + h0.w * z.w;
            a[1] = h1.x * z.x + h1.y * z.y + h1.z * z.z + h1.w * z.w;
            a[2] = h2.x * z.x + h2.y * z.y + h2.z * z.z + h2.w * z.w;
            a[3] = h3.x * z.x + h3.y * z.y + h3.z * z.z + h3.w * z.w;
        }
        {
            float4 h4 = __ldg(Wm1 + (size_t)(b >> (DEPTH - 4)) * 32);
            float4 h5 = __ldg(Wm1 + (size_t)(b >> (DEPTH - 5)) * 32);
            float4 h6 = __ldg(Wm1 + (size_t)(b >> (DEPTH - 6)) * 32);
            a[4] = h4.x * z.x + h4.y * z.y + h4.z * z.z + h4.w * z.w;
            a[5] = h5.x * z.x + h5.y * z.y + h5.z * z.z + h5.w * z.w;
            a[6] = h6.x * z.x + h6.y * z.y + h6.z * z.z + h6.w * z.w;
        }

        // --- deep dot products (frees w[], z) ---
#pragma unroll
        for (int j = 0; j < NDEEP; ++j)
            a[7 + j] = w[j].x * z.x + w[j].y * z.y + w[j].z * z.z + w[j].w * z.w;

        // --- issue next element's deep burst into the freed registers ---
        const bool have_next = (e1 < BATCH);
        if (have_next) {
            z = __ldg(Wl + (size_t)((unsigned)cv1.x + OFFSET) * 32);
            const unsigned bn = (unsigned)cv1.y + OFFSET + 1u;
#pragma unroll
            for (int j = 0; j < NDEEP; ++j)
                w[j] = __ldg(Wm1 + (size_t)(bn >> (NDEEP - 1 - j)) * 32);
            b = bn;
        }

        // --- pruned compaction transpose-reduce (23 shuffles), after burst ---
        // out-of-range partner slots (21, 22, 24) are explicit zeros.
        {
            const bool hi = (lane & 1) != 0;
#pragma unroll
            for (int k = 0; k < 20; k += 2) {
                const float send = hi ? a[k] : a[k + 1];
                const float recv = __shfl_xor_sync(0xFFFFFFFFu, send, 1);
                a[k] = (hi ? a[k + 1] : a[k]) + recv;
            }
            {   // k = 20, partner slot 21 == 0
                const float send = hi ? a[20] : 0.0f;
                const float recv = __shfl_xor_sync(0xFFFFFFFFu, send, 1);
                a[20] = (hi ? 0.0f : a[20]) + recv;
            }
        }
        {
            const bool hi = (lane & 2) != 0;
#pragma unroll
            for (int k = 0; k < 20; k += 4) {
                const float send = hi ? a[k] : a[k + 2];
                const float recv = __shfl_xor_sync(0xFFFFFFFFu, send, 2);
                a[k] = (hi ? a[k + 2] : a[k]) + recv;
            }
            {   // k = 20, partner slot 22 == 0
                const float send = hi ? a[20] : 0.0f;
                const float recv = __shfl_xor_sync(0xFFFFFFFFu, send, 2);
                a[20] = (hi ? 0.0f : a[20]) + recv;
            }
        }
        {
            const bool hi = (lane & 4) != 0;
#pragma unroll
            for (int k = 0; k < 24; k += 8) {   // k = 0, 8, 16 (partners 4, 12, 20)
                const float send = hi ? a[k] : a[k + 4];
                const float recv = __shfl_xor_sync(0xFFFFFFFFu, send, 4);
                a[k] = (hi ? a[k + 4] : a[k]) + recv;
            }
        }
        {
            const bool hi = (lane & 8) != 0;
            {   // k = 0, partner 8
                const float send = hi ? a[0] : a[8];
                const float recv = __shfl_xor_sync(0xFFFFFFFFu, send, 8);
                a[0] = (hi ? a[8] : a[0]) + recv;
            }
            {   // k = 16, partner slot 24 == 0
                const float send = hi ? a[16] : 0.0f;
                const float recv = __shfl_xor_sync(0xFFFFFFFFu, send, 8);
                a[16] = (hi ? 0.0f : a[16]) + recv;
            }
        }
        {
            const bool hi = (lane & 16) != 0;
            const float send = hi ? a[0] : a[16];
            const float recv = __shfl_xor_sync(0xFFFFFFFFu, send, 16);
            a[0] = (hi ? a[16] : a[0]) + recv;
        }

        // lane l (< 21) holds s_l; one SIMT EX2 covers all levels
        float c = (lane < NPATH) ? (1.0f + __expf(-a[0])) : 1.0f;
#pragma unroll
        for (int o = 16; o > 0; o >>= 1)
            c *= __shfl_xor_sync(0xFFFFFFFFu, c, o);

        if (lane == 0) out[e] = __fdividef(1.0f, c);

        if (!have_next) return;
        e   = e1;
        e1  = e2;
        cv1 = cv2;
    }
}

extern "C" void kernel_launch(void* const* d_in, const int* in_sizes, int n_in,
                              void* d_out, int out_size)
{
    const int*   coll = (const int*)d_in[0];
    const float* W    = (const float*)d_in[1];
    float*       out  = (float*)d_out;

    // 2-warp blocks: warps/SM degrades linearly with regs, no 4-warp cliff.
    // Exactly one resident wave, sized from measured occupancy.
    const int threads = 64;
    int bpsm = 8;
    cudaOccupancyMaxActiveBlocksPerMultiprocessor(
        &bpsm, BinaryTree_65927747993695_kernel, threads, 0);
    if (bpsm < 1) bpsm = 1;
    long long blocks = (long long)bpsm * 148;
    if (blocks > BATCH / 2) blocks = BATCH / 2;
    BinaryTree_65927747993695_kernel<<<(int)blocks, threads>>>(coll, W, out);
}